// round 16
// baseline (speedup 1.0000x reference)
#include <cuda_runtime.h>
#include <cuda_bf16.h>
#include <math.h>
#include <stdint.h>

#define BATCH 8
#define P0    4608
#define CDIM  1024
#define HEADS 16
#define DDIM  64
#define HDIM  4096
#define NMAX  2304
#define TOUT  128

// ---------------- PTX helpers (sm_103 baseline ISA only) ----------------
__device__ __forceinline__ uint32_t smem_u32(const void* p) {
    uint32_t a;
    asm("{ .reg .u64 t; cvta.to.shared.u64 t, %1; cvt.u32.u64 %0, t; }" : "=r"(a) : "l"(p));
    return a;
}
__device__ __forceinline__ void ldsm4(uint32_t* r, uint32_t addr) {
    asm volatile("ldmatrix.sync.aligned.m8n8.x4.shared.b16 {%0,%1,%2,%3}, [%4];"
        : "=r"(r[0]), "=r"(r[1]), "=r"(r[2]), "=r"(r[3]) : "r"(addr));
}
__device__ __forceinline__ void mma_bf16(float* c, const uint32_t* a, uint32_t b0, uint32_t b1) {
    asm volatile("mma.sync.aligned.m16n8k16.row.col.f32.bf16.bf16.f32 "
        "{%0,%1,%2,%3}, {%4,%5,%6,%7}, {%8,%9}, {%0,%1,%2,%3};"
        : "+f"(c[0]), "+f"(c[1]), "+f"(c[2]), "+f"(c[3])
        : "r"(a[0]), "r"(a[1]), "r"(a[2]), "r"(a[3]), "r"(b0), "r"(b1));
}
#define CP_ASYNC(dst, src) asm volatile("cp.async.cg.shared.global [%0], [%1], 16;" :: "r"(dst), "l"(src))
#define CP_COMMIT()        asm volatile("cp.async.commit_group;" ::: "memory")
#define CP_WAIT(n)         asm volatile("cp.async.wait_group %0;" :: "n"(n) : "memory")

// ---------------- scratch ----------------
__device__ float g_bufA[(size_t)BATCH * 1152 * CDIM];
__device__ float g_bufB[(size_t)BATCH * NMAX * CDIM];
__device__ float g_sizeA[BATCH * 1152];
__device__ float g_sizeB[BATCH * NMAX];
__device__ __nv_bfloat16 g_msplit[(size_t)BATCH * P0 * 192];   // [h1|h2|h3] per token
__device__ float g_nodemax[BATCH * NMAX];
__device__ int   g_nodeidx[BATCH * NMAX];
__device__ float g_hsum[(size_t)BATCH * NMAX * 64];
__device__ float g_possum[P0 * 64];
__device__ int   g_edge[BATCH * 72];
__device__ __nv_bfloat16 g_A1[(size_t)1024 * 2048];    // GEMM1 A' [hi|lo]
__device__ __nv_bfloat16 g_A2[(size_t)1024 * 8192];    // GEMM2 A' [hi|lo]
__device__ __nv_bfloat16 g_W1b[(size_t)4096 * 2048];   // W1' [N,2K] [hi|lo]
__device__ __nv_bfloat16 g_W2b[(size_t)4096 * 8192];   // W2' [N,2K] [hi|lo]

__device__ __forceinline__ void bsplit(float x, unsigned short& h, unsigned short& l) {
    __nv_bfloat16 hb = __float2bfloat16(x);
    float r = x - __bfloat162float(hb);
    __nv_bfloat16 lb = __float2bfloat16(r);
    h = __bfloat16_as_ushort(hb);
    l = __bfloat16_as_ushort(lb);
}

__device__ __forceinline__ void msplit_write(__nv_bfloat16* o, int d, float v) {
    __nv_bfloat16 h1 = __float2bfloat16(v);
    float r1v = v - __bfloat162float(h1);
    __nv_bfloat16 h2 = __float2bfloat16(r1v);
    float r2v = r1v - __bfloat162float(h2);
    __nv_bfloat16 h3 = __float2bfloat16(r2v);
    o[d] = h1; o[64 + d] = h2; o[128 + d] = h3;
}

// ---------------- pos head-sum precompute: possum[t][d] = sum_h pos[t][h*64+d] ----------------
__global__ __launch_bounds__(256) void k_possum(const float* __restrict__ pos,
        float* __restrict__ possum)
{
    int idx = blockIdx.x * 256 + threadIdx.x;   // 4608*64 total
    int t = idx >> 6, d = idx & 63;
    const float* pb = pos + (size_t)t * CDIM;
    float s = 0.f;
    #pragma unroll
    for (int h = 0; h < HEADS; ++h) s += pb[h * DDIM + d];
    possum[idx] = s;
}

// ---------------- metric round 1: from x (strided) + possum, 4 tokens/block ----------------
__global__ __launch_bounds__(256) void k_metric(const float* __restrict__ ws,
        const float* __restrict__ possum, __nv_bfloat16* __restrict__ msplit, int p)
{
    int tid = threadIdx.x;
    int sub = tid >> 6;
    int d   = tid & 63;
    int t   = blockIdx.x * 4 + sub;
    int tok = t % p;
    const float* base = ws + (size_t)t * CDIM;
    float s = 0.f;
    #pragma unroll
    for (int h = 0; h < HEADS; ++h) s += base[h * DDIM + d];
    s += possum[tok * 64 + d];
    float m = s * (1.f / 16.f);
    __shared__ float red[256];
    red[tid] = m * m;
    __syncthreads();
    for (int off = 32; off > 0; off >>= 1) {
        if (d < off) red[tid] += red[tid + off];
        __syncthreads();
    }
    float nrm = sqrtf(red[sub * 64]);
    msplit_write(msplit + (size_t)t * 192, d, m / nrm);
}

// ---------------- metric rounds 2-6: from 64-dim head-sums, 4 tokens/block ----------------
__global__ __launch_bounds__(256) void k_metric_h(const float* __restrict__ hsum,
        __nv_bfloat16* __restrict__ msplit)
{
    int tid = threadIdx.x;
    int sub = tid >> 6;
    int d   = tid & 63;
    int t   = blockIdx.x * 4 + sub;
    float m = hsum[(size_t)t * 64 + d] * (1.f / 16.f);
    __shared__ float red[256];
    red[tid] = m * m;
    __syncthreads();
    for (int off = 32; off > 0; off >>= 1) {
        if (d < off) red[tid] += red[tid + off];
        __syncthreads();
    }
    float nrm = sqrtf(red[sub * 64]);
    msplit_write(msplit + (size_t)t * 192, d, m / nrm);
}

// ---------------- tensor-core scores + row argmax, bf16x6, cp.async triple-buffered B ----------------
#define AMSPAD 200
#define ABUF (128 * AMSPAD * 2)

__global__ __launch_bounds__(256) void k_argmax(const __nv_bfloat16* __restrict__ msplit,
        float* __restrict__ nodemax, int* __restrict__ nodeidx, int n, int p)
{
    extern __shared__ __align__(16) char dyn[];
    __nv_bfloat16* sA = (__nv_bfloat16*)dyn;
    uint32_t saA  = smem_u32(sA);
    uint32_t saB  = saA + 64 * AMSPAD * 2;      // 3 x [128][AMSPAD]
    float* sv = (float*)(dyn + 64 * AMSPAD * 2 + 3 * ABUF);
    int*   sj = (int*)  (dyn + 64 * AMSPAD * 2 + 3 * ABUF + 4 * 64 * 4);

    int b = blockIdx.y;
    int ibase = blockIdx.x * 64;
    const __nv_bfloat16* M = msplit + (size_t)b * p * 192;
    int tid = threadIdx.x;
    int wid = tid >> 5, lane = tid & 31;
    int wm = wid >> 2, wn = wid & 3;
    int g = lane >> 2, tg = lane & 3;

    int ntiles = (n + 127) >> 7;

    // prologue: A resident + B tile 0 (one group), then B tile 1 (second group)
    for (int o = tid; o < 64 * 24; o += 256) {
        int r = o / 24, s = o % 24;
        CP_ASYNC(saA + (uint32_t)(r * AMSPAD + s * 8) * 2,
                 M + (size_t)(2 * (ibase + r)) * 192 + s * 8);
    }
    for (int o = tid; o < 128 * 24; o += 256) {
        int r = o / 24, s = o % 24;
        CP_ASYNC(saB + (uint32_t)(r * AMSPAD + s * 8) * 2,
                 M + (size_t)(2 * r + 1) * 192 + s * 8);
    }
    CP_COMMIT();
    if (ntiles > 1) {
        for (int o = tid; o < 128 * 24; o += 256) {
            int r = o / 24, s = o % 24;
            CP_ASYNC(saB + ABUF + (uint32_t)(r * AMSPAD + s * 8) * 2,
                     M + (size_t)(2 * (128 + r) + 1) * 192 + s * 8);
        }
        CP_COMMIT();
    }

    float runv[4]; int runj[4];
    #pragma unroll
    for (int q = 0; q < 4; q++) { runv[q] = -1e30f; runj[q] = 0x7FFFFFFF; }

    const int amap[6] = {0, 0, 1, 1, 0, 2};
    const int bmap[6] = {0, 1, 0, 1, 2, 0};

    for (int jt = 0; jt < ntiles; jt++) {
        int jbase = jt << 7;
        uint32_t cb = saB + (uint32_t)(jt % 3) * ABUF;
        if (jt + 2 < ntiles) {
            uint32_t nb = saB + (uint32_t)((jt + 2) % 3) * ABUF;
            int jb2 = (jt + 2) << 7;
            for (int o = tid; o < 128 * 24; o += 256) {
                int r = o / 24, s = o % 24;
                CP_ASYNC(nb + (uint32_t)(r * AMSPAD + s * 8) * 2,
                         M + (size_t)(2 * (jb2 + r) + 1) * 192 + s * 8);
            }
            CP_COMMIT();
            CP_WAIT(2);
        } else if (jt + 1 < ntiles) {
            CP_WAIT(1);
        } else {
            CP_WAIT(0);
        }
        __syncthreads();   // tile jt (and A) ready for all threads

        float acc[2][4][4];
        #pragma unroll
        for (int mt = 0; mt < 2; mt++)
            #pragma unroll
            for (int nt = 0; nt < 4; nt++)
                #pragma unroll
                for (int q = 0; q < 4; q++) acc[mt][nt][q] = 0.f;

        #pragma unroll
        for (int blk = 0; blk < 6; blk++) {
            #pragma unroll
            for (int qk = 0; qk < 4; qk++) {
                int ca = amap[blk] * 64 + qk * 16 + (lane >> 4) * 8;
                int cbo = bmap[blk] * 64 + qk * 16 + (lane >> 4) * 8;
                uint32_t a[2][4], bb[2][4];
                #pragma unroll
                for (int mt = 0; mt < 2; mt++)
                    ldsm4(a[mt], saA + (uint32_t)((wm * 32 + mt * 16 + (lane & 15)) * AMSPAD + ca) * 2);
                #pragma unroll
                for (int nt2 = 0; nt2 < 2; nt2++)
                    ldsm4(bb[nt2], cb + (uint32_t)((wn * 32 + nt2 * 16 + (lane & 15)) * AMSPAD + cbo) * 2);
                #pragma unroll
                for (int mt = 0; mt < 2; mt++)
                    #pragma unroll
                    for (int nt = 0; nt < 4; nt++)
                        mma_bf16(acc[mt][nt], a[mt], bb[nt >> 1][nt & 1], bb[nt >> 1][(nt & 1) + 2]);
            }
        }

        #pragma unroll
        for (int mt = 0; mt < 2; mt++) {
            #pragma unroll
            for (int h = 0; h < 2; h++) {
                float bv = -1e30f; int bj = 0x7FFFFFFF;
                #pragma unroll
                for (int nt = 0; nt < 4; nt++) {
                    #pragma unroll
                    for (int q = 0; q < 2; q++) {
                        int jg = jbase + wn * 32 + nt * 8 + tg * 2 + q;
                        float v = acc[mt][nt][h * 2 + q];
                        if (jg < n && v > bv) { bv = v; bj = jg; }
                    }
                }
                int slot = mt * 2 + h;
                if (bv > runv[slot] || (bv == runv[slot] && bj < runj[slot])) {
                    runv[slot] = bv; runj[slot] = bj;
                }
            }
        }
        __syncthreads();   // all reads of cb done before its buffer is rewritten
    }

    #pragma unroll
    for (int slot = 0; slot < 4; slot++) {
        float bv = runv[slot]; int bj = runj[slot];
        #pragma unroll
        for (int off = 1; off <= 2; off <<= 1) {
            float ov = __shfl_xor_sync(0xffffffffu, bv, off);
            int   oj = __shfl_xor_sync(0xffffffffu, bj, off);
            if (ov > bv || (ov == bv && oj < bj)) { bv = ov; bj = oj; }
        }
        runv[slot] = bv; runj[slot] = bj;
    }
    if (tg == 0) {
        #pragma unroll
        for (int slot = 0; slot < 4; slot++) {
            int mt = slot >> 1, h = slot & 1;
            int row = wm * 32 + mt * 16 + h * 8 + g;
            sv[wn * 64 + row] = runv[slot];
            sj[wn * 64 + row] = runj[slot];
        }
    }
    __syncthreads();
    if (tid < 64) {
        float bv = sv[tid]; int bj = sj[tid];
        #pragma unroll
        for (int w = 1; w < 4; w++) {
            float ov = sv[w * 64 + tid]; int oj = sj[w * 64 + tid];
            if (ov > bv || (ov == bv && oj < bj)) { bv = ov; bj = oj; }
        }
        int ig = ibase + tid;
        if (ig < n) {
            nodemax[b * NMAX + ig] = bv;
            nodeidx[b * NMAX + ig] = bj;
        }
    }
}
#define ARGMAX_SMEM (64 * AMSPAD * 2 + 3 * ABUF + 4 * 64 * 4 * 2)

// ---------------- rounds 1-5 merge (scatter-based, with head-sum emission) ----------------
__global__ void k_dst_init(const float* __restrict__ ws, const float* __restrict__ pos,
        const float* __restrict__ szin, float* __restrict__ wsout, float* __restrict__ szout,
        float* __restrict__ hsum, int n, int p)
{
    __shared__ float sred[1024];
    int blk = blockIdx.x;
    int b = blk / n, j = blk % n;
    const float4* src = (const float4*)(ws + ((size_t)b * p + 2 * j + 1) * CDIM);
    float4* dst = (float4*)(wsout + ((size_t)b * n + j) * CDIM);
    int c = threadIdx.x;
    float4 v = src[c];
    if (pos) {
        const float4* pb = (const float4*)(pos + (size_t)(2 * j + 1) * CDIM);
        float4 pv = pb[c];
        v.x += pv.x; v.y += pv.y; v.z += pv.z; v.w += pv.w;
    }
    dst[c] = v;
    int c0 = c * 4;
    sred[c0] = v.x; sred[c0 + 1] = v.y; sred[c0 + 2] = v.z; sred[c0 + 3] = v.w;
    if (threadIdx.x == 0) szout[b * n + j] = szin ? szin[b * p + 2 * j + 1] : 1.f;
    __syncthreads();
    if (threadIdx.x < 64) {
        float s = 0.f;
        #pragma unroll
        for (int k = 0; k < 16; k++) s += sred[threadIdx.x + 64 * k];
        hsum[((size_t)b * n + j) * 64 + threadIdx.x] = s;
    }
}

__global__ void k_scatter(const float* __restrict__ ws, const float* __restrict__ pos,
        const float* __restrict__ szin, const int* __restrict__ nodeidx,
        float* __restrict__ wsout, float* __restrict__ szout, float* __restrict__ hsum,
        int n, int p)
{
    __shared__ float sred[1024];
    int blk = blockIdx.x;
    int b = blk / n, i = blk % n;
    int j = nodeidx[b * NMAX + i];
    const float* src = ws + ((size_t)b * p + 2 * i) * CDIM;
    float* dst = wsout + ((size_t)b * n + j) * CDIM;
    if (pos) {
        const float* pb = pos + (size_t)(2 * i) * CDIM;
        for (int c = threadIdx.x; c < CDIM; c += 256) {
            float val = src[c] + pb[c];
            atomicAdd(dst + c, val);
            sred[c] = val;
        }
    } else {
        for (int c = threadIdx.x; c < CDIM; c += 256) {
            float val = src[c];
            atomicAdd(dst + c, val);
            sred[c] = val;
        }
    }
    if (threadIdx.x == 0) atomicAdd(szout + b * n + j, szin ? szin[b * p + 2 * i] : 1.f);
    __syncthreads();
    if (threadIdx.x < 64) {
        float s = 0.f;
        #pragma unroll
        for (int k = 0; k < 16; k++) s += sred[threadIdx.x + 64 * k];
        atomicAdd(&hsum[((size_t)b * n + j) * 64 + threadIdx.x], s);
    }
}

// ---------------- round 6 ----------------
__global__ void k_sort6(const float* __restrict__ nodemax, int* __restrict__ edge)
{
    __shared__ float v[72];
    int b = blockIdx.x, t = threadIdx.x;
    if (t < 72) v[t] = nodemax[b * NMAX + t];
    __syncthreads();
    if (t < 72) {
        float mv = v[t];
        int rank = 0;
        for (int j2 = 0; j2 < 72; j2++) {
            float o = v[j2];
            if (o > mv || (o == mv && j2 < t)) rank++;
        }
        edge[b * 72 + rank] = t;
    }
}

__global__ void k_round6(const float* __restrict__ ws, const float* __restrict__ sz,
        const int* __restrict__ nodeidx, const int* __restrict__ edge,
        __nv_bfloat16* __restrict__ A1)
{
    const int p = 144, r = 16, u = 56;
    int b = blockIdx.y, t = blockIdx.x;
    int tid = threadIdx.x;
    const float* wsb = ws + (size_t)b * p * CDIM;
    int m = b * 128 + t;
    __nv_bfloat16* rowp = A1 + (size_t)m * 2048;
    int c0 = tid * 4;

    float v[4];
    float s;
    if (t < u) {
        int e = edge[b * 72 + r + t];
        const float4 vv = ((const float4*)(wsb + (size_t)(2 * e) * CDIM))[tid];
        v[0] = vv.x; v[1] = vv.y; v[2] = vv.z; v[3] = vv.w;
        s = sz[b * p + 2 * e];
    } else {
        int j = t - u;
        __shared__ int msrc[16];
        __shared__ int mcount;
        __shared__ float ssum_sh;
        if (tid == 0) {
            int cnt = 0;
            float ssum = sz[b * p + 2 * j + 1];
            for (int q = 0; q < r; q++) {
                int e = edge[b * 72 + q];
                if (nodeidx[b * NMAX + e] == j) { msrc[cnt++] = 2 * e; ssum += sz[b * p + 2 * e]; }
            }
            mcount = cnt;
            ssum_sh = ssum;
        }
        __syncthreads();
        int cnt = mcount;
        s = ssum_sh;
        const float4 base4 = ((const float4*)(wsb + (size_t)(2 * j + 1) * CDIM))[tid];
        v[0] = base4.x; v[1] = base4.y; v[2] = base4.z; v[3] = base4.w;
        for (int q = 0; q < cnt; q++) {
            const float4 a4 = ((const float4*)(wsb + (size_t)msrc[q] * CDIM))[tid];
            v[0] += a4.x; v[1] += a4.y; v[2] += a4.z; v[3] += a4.w;
        }
    }
    float inv = 1.f / s;
    unsigned short hh[4], ll[4];
    #pragma unroll
    for (int q = 0; q < 4; q++) bsplit(v[q] * inv, hh[q], ll[q]);
    uint2 hp, lp;
    hp.x = (uint32_t)hh[0] | ((uint32_t)hh[1] << 16);
    hp.y = (uint32_t)hh[2] | ((uint32_t)hh[3] << 16);
    lp.x = (uint32_t)ll[0] | ((uint32_t)ll[1] << 16);
    lp.y = (uint32_t)ll[2] | ((uint32_t)ll[3] << 16);
    *(uint2*)(rowp + c0)        = hp;
    *(uint2*)(rowp + 1024 + c0) = lp;
}

// ---------------- conversions ----------------
__global__ void k_convW(const float* __restrict__ W, __nv_bfloat16* __restrict__ Bp,
                        int K, int N)
{
    __shared__ float tile[32][33];
    int n0 = blockIdx.x * 32, k0 = blockIdx.y * 32;
    int tx = threadIdx.x & 31, ty = threadIdx.x >> 5;
    #pragma unroll
    for (int i = 0; i < 4; i++)
        tile[ty + 8 * i][tx] = W[(size_t)(k0 + ty + 8 * i) * N + n0 + tx];
    __syncthreads();
    size_t s2K = (size_t)2 * K;
    #pragma unroll
    for (int i = 0; i < 4; i++) {
        float v = tile[tx][ty + 8 * i];
        unsigned short h, l;
        bsplit(v, h, l);
        __nv_bfloat16* row = Bp + (size_t)(n0 + ty + 8 * i) * s2K + k0 + tx;
        row[0] = __ushort_as_bfloat16(h);
        row[K] = __ushort_as_bfloat16(l);
    }
}

// ---------------- warp-MMA bf16 GEMM (MLP), BK=32, 3-stage, deduped [hi|lo] storage ----------------
#define SMPAD 40
#define MMBUF (128 * SMPAD * 2)        // 10240 bytes per stage per matrix
#define MM_SMEM (6 * MMBUF)            // 3 stages x (A+B) = 61440

template<int EPI>
__global__ __launch_bounds__(256) void k_mma(
    const __nv_bfloat16* __restrict__ A, int lda,
    const __nv_bfloat16* __restrict__ B, int ldb,
    const float* __restrict__ bias,
    float* __restrict__ outF, __nv_bfloat16* __restrict__ outS, int K, int nchunk3)
{
    extern __shared__ __align__(16) char dynm[];
    uint32_t saA = smem_u32(dynm);             // 3 x MMBUF
    uint32_t saB = saA + 3 * MMBUF;            // 3 x MMBUF

    int tid = threadIdx.x;
    int wid = tid >> 5, lane = tid & 31;
    int wm = wid >> 2, wn = wid & 3;
    int m0 = blockIdx.y * 128, n0 = blockIdx.x * 128;

    float acc[4][4][4];
    #pragma unroll
    for (int i = 0; i < 4; i++)
        #pragma unroll
        for (int j = 0; j < 4; j++)
            #pragma unroll
            for (int q = 0; q < 4; q++) acc[i][j][q] = 0.f;

    int lrow = tid >> 2;
    int lseg = tid & 3;
    uint32_t soff0 = (uint32_t)(lrow * SMPAD + lseg * 8) * 2;
    uint32_t soff1 = (uint32_t)((lrow + 64) * SMPAD + lseg * 8) * 2;

    const __nv_bfloat16* Abase = A + (size_t)(m0 + lrow) * lda + lseg * 8;
    const __nv_bfloat16* Bbase = B + (size_t)(n0 + lrow) * ldb + lseg * 8;
    size_t astep64 = (size_t)64 * lda;
    size_t bstep64 = (size_t)64 * ldb;

    int ntile = K >> 5;

    auto issue = [&](int ic, int stage) {
        int blk = ic / nchunk3;
        int rem = ic - blk * nchunk3;
        int achunk = ((blk == 1) ? nchunk3 : 0) + rem;
        int bchunk = ((blk == 2) ? nchunk3 : 0) + rem;
        const __nv_bfloat16* Ap = Abase + (size_t)achunk * 32;
        const __nv_bfloat16* Bp = Bbase + (size_t)bchunk * 32;
        uint32_t da = saA + stage * MMBUF;
        uint32_t db = saB + stage * MMBUF;
        CP_ASYNC(da + soff0, Ap);
        CP_ASYNC(da + soff1, Ap + astep64);
        CP_ASYNC(db + soff0, Bp);
        CP_ASYNC(db + soff1, Bp + bstep64);
        CP_COMMIT();
    };

    // prologue: stages 0 and 1
    issue(0, 0);
    if (ntile > 1) issue(1, 1);

    for (int it = 0; it < ntile; it++) {
        int stage = it % 3;
        if (it + 2 < ntile) {
            issue(it + 2, (it + 2) % 3);
            CP_WAIT(2);
        } else if (it + 1 < ntile) {
            CP_WAIT(1);
        } else {
            CP_WAIT(0);
        }
        __syncthreads();

        uint32_t bufA = saA + stage * MMBUF;
        uint32_t bufB2 = saB + stage * MMBUF;
        #pragma unroll
        for (int ks = 0; ks < 2; ks++) {
            uint32_t a[4][4], b[2][4];
            int c = ks * 16 + (lane >> 4) * 8;
            #pragma unroll
            for (int mt = 0; mt < 4; mt++) {
                int r = wm * 64 + mt * 16 + (lane & 15);
                ldsm4(a[mt], bufA + (uint32_t)(r * SMPAD + c) * 2);
            }
            #pragma unroll
            for (int nt2 = 0; nt2 < 2; nt2++) {
                int r = wn * 32 + nt2 * 16 + (lane & 15);
                ldsm4(b[nt2], bufB2 + (uint32_t)(r * SMPAD + c) * 2);
            }
            #pragma unroll
            for (int mt = 0; mt < 4; mt++)
                #pragma unroll
                for (int nt = 0; nt < 4; nt++)
                    mma_bf16(acc[mt][nt], a[mt], b[nt >> 1][nt & 1], b[nt >> 1][(nt & 1) + 2]);
        }
        __syncthreads();
    }

    int g = lane >> 2, tg = lane & 3;
    #pragma unroll
    for (int mt = 0; mt < 4; mt++) {
        #pragma unroll
        for (int half = 0; half < 2; half++) {
            int m = m0 + wm * 64 + mt * 16 + g + half * 8;
            #pragma unroll
            for (int nt = 0; nt < 4; nt++) {
                int col = n0 + wn * 32 + nt * 8 + tg * 2;
                float2 bb = *(const float2*)(bias + col);
                float v0 = acc[mt][nt][half * 2 + 0] + bb.x;
                float v1 = acc[mt][nt][half * 2 + 1] + bb.y;
                if (EPI == 1) {
                    v0 = 0.5f * v0 * (1.f + erff(v0 * 0.70710678118654752f));
                    v1 = 0.5f * v1 * (1.f + erff(v1 * 0.70710678118654752f));
                    unsigned short h0, l0, h1, l1;
                    bsplit(v0, h0, l0);
                    bsplit(v1, h1, l1);
                    uint32_t hp = (uint32_t)h0 | ((uint32_t)h1 << 16);
                    uint32_t lp = (uint32_t)l0 | ((uint32_t)l1 << 16);
                    __nv_bfloat16* rowp = outS + (size_t)m * 8192;
                    *(uint32_t*)(rowp + col)        = hp;
                    *(uint32_t*)(rowp + col + 4096) = lp;
                } else {
                    float2 o; o.x = v0; o.y = v1;
                    *(float2*)(outF + (size_t)m * 4096 + col) = o;
                }
            }
        }
    }
}

// ---------------- launcher ----------------
extern "C" void kernel_launch(void* const* d_in, const int* in_sizes, int n_in,
                              void* d_out, int out_size)
{
    const float* x   = (const float*)d_in[0];
    const float* pos = (const float*)d_in[1];
    const float* W1  = (const float*)d_in[2];
    const float* b1  = (const float*)d_in[3];
    const float* W2  = (const float*)d_in[4];
    const float* b2  = (const float*)d_in[5];
    float* out = (float*)d_out;

    float *bufA, *bufB, *szA, *szB, *nmax, *hsum, *possum;
    int *nidx, *edge;
    __nv_bfloat16 *msplit, *A1, *A2, *W1b, *W2b;
    cudaGetSymbolAddress((void**)&bufA,   g_bufA);
    cudaGetSymbolAddress((void**)&bufB,   g_bufB);
    cudaGetSymbolAddress((void**)&szA,    g_sizeA);
    cudaGetSymbolAddress((void**)&szB,    g_sizeB);
    cudaGetSymbolAddress((void**)&msplit, g_msplit);
    cudaGetSymbolAddress((void**)&nmax,   g_nodemax);
    cudaGetSymbolAddress((void**)&nidx,   g_nodeidx);
    cudaGetSymbolAddress((void**)&hsum,   g_hsum);
    cudaGetSymbolAddress((void**)&possum, g_possum);
    cudaGetSymbolAddress((void**)&edge,   g_edge);
    cudaGetSymbolAddress((void**)&A1,     g_A1);
    cudaGetSymbolAddress((void**)&A2,     g_A2);
    cudaGetSymbolAddress((void**)&W1b,    g_W1b);
    cudaGetSymbolAddress((void**)&W2b,    g_W2b);

    cudaFuncSetAttribute(k_argmax, cudaFuncAttributeMaxDynamicSharedMemorySize, ARGMAX_SMEM);
    cudaFuncSetAttribute(k_mma<1>, cudaFuncAttributeMaxDynamicSharedMemorySize, MM_SMEM);
    cudaFuncSetAttribute(k_mma<0>, cudaFuncAttributeMaxDynamicSharedMemorySize, MM_SMEM);

    // weight conversions + pos head-sum (independent of merge results)
    k_possum<<<P0 * 64 / 256, 256>>>(pos, possum);
    k_convW<<<dim3(4096 / 32, 1024 / 32), 256>>>(W1, W1b, 1024, 4096);
    k_convW<<<dim3(4096 / 32, 4096 / 32), 256>>>(W2, W2b, 4096, 4096);

    // Round 1: p=4608, n=r=2304
    k_metric<<<BATCH * 4608 / 4, 256>>>(x, possum, msplit, 4608);
    k_argmax<<<dim3(36, BATCH), 256, ARGMAX_SMEM>>>(msplit, nmax, nidx, 2304, 4608);
    k_dst_init<<<BATCH * 2304, 256>>>(x, pos, nullptr, bufB, szB, hsum, 2304, 4608);
    k_scatter<<<BATCH * 2304, 256>>>(x, pos, nullptr, nidx, bufB, szB, hsum, 2304, 4608);

    // Round 2
    k_metric_h<<<BATCH * 2304 / 4, 256>>>(hsum, msplit);
    k_argmax<<<dim3(18, BATCH), 256, ARGMAX_SMEM>>>(msplit, nmax, nidx, 1152, 2304);
    k_dst_init<<<BATCH * 1152, 256>>>(bufB, nullptr, szB, bufA, szA, hsum, 1152, 2304);
    k_scatter<<<BATCH * 1152, 256>>>(bufB, nullptr, szB, nidx, bufA, szA, hsum, 1152, 2304);

    // Round 3
    k_metric_h<<<BATCH * 1152 / 4, 256>>>(hsum, msplit);
    k_argmax<<<dim3(9, BATCH), 256, ARGMAX_SMEM>>>(msplit, nmax, nidx, 576, 1152);
    k_dst_init<<<BATCH * 576, 256>>>(bufA, nullptr, szA, bufB, szB, hsum, 576, 1152);
    k_scatter<<<BATCH * 576, 256>>>(bufA, nullptr, szA, nidx, bufB, szB, hsum, 576, 1152);

    // Round 4
    k_metric_h<<<BATCH * 576 / 4, 256>>>(hsum, msplit);
    k_argmax<<<dim3(5, BATCH), 256, ARGMAX_SMEM>>>(msplit, nmax, nidx, 288, 576);
    k_dst_init<<<BATCH * 288, 256>>>(bufB, nullptr, szB, bufA, szA, hsum, 288, 576);
    k_scatter<<<BATCH * 288, 256>>>(bufB, nullptr, szB, nidx, bufA, szA, hsum, 288, 576);

    // Round 5
    k_metric_h<<<BATCH * 288 / 4, 256>>>(hsum, msplit);
    k_argmax<<<dim3(3, BATCH), 256, ARGMAX_SMEM>>>(msplit, nmax, nidx, 144, 288);
    k_dst_init<<<BATCH * 144, 256>>>(bufA, nullptr, szA, bufB, szB, hsum, 144, 288);
    k_scatter<<<BATCH * 144, 256>>>(bufA, nullptr, szA, nidx, bufB, szB, hsum, 144, 288);

    // Round 6: p=144, n=72, r=16 (needs sort); fused output -> A1 [hi|lo]
    k_metric_h<<<BATCH * 144 / 4, 256>>>(hsum, msplit);
    k_argmax<<<dim3(2, BATCH), 256, ARGMAX_SMEM>>>(msplit, nmax, nidx, 72, 144);
    k_sort6<<<BATCH, 128>>>(nmax, edge);
    k_round6<<<dim3(128, BATCH), 256>>>(bufB, szB, nidx, edge, A1);

    // GEMM1: gelu((A/sz)@W1+b1) -> [hi|lo] into A2. logical K=3072, nchunk3=32
    k_mma<1><<<dim3(32, 8), 256, MM_SMEM>>>(A1, 2048, W1b, 2048, b1, nullptr, A2, 3072, 32);
    // GEMM2: A2@W2+b2 -> out fp32. logical K=12288, nchunk3=128
    k_mma<0><<<dim3(32, 8), 256, MM_SMEM>>>(A2, 8192, W2b, 8192, b2, out, nullptr, 12288, 128);
}

// round 17
// speedup vs baseline: 1.0337x; 1.0337x over previous
#include <cuda_runtime.h>
#include <cuda_bf16.h>
#include <math.h>
#include <stdint.h>

#define BATCH 8
#define P0    4608
#define CDIM  1024
#define HEADS 16
#define DDIM  64
#define HDIM  4096
#define NMAX  2304
#define TOUT  128

// ---------------- PTX helpers (sm_103 baseline ISA only) ----------------
__device__ __forceinline__ uint32_t smem_u32(const void* p) {
    uint32_t a;
    asm("{ .reg .u64 t; cvta.to.shared.u64 t, %1; cvt.u32.u64 %0, t; }" : "=r"(a) : "l"(p));
    return a;
}
__device__ __forceinline__ void ldsm4(uint32_t* r, uint32_t addr) {
    asm volatile("ldmatrix.sync.aligned.m8n8.x4.shared.b16 {%0,%1,%2,%3}, [%4];"
        : "=r"(r[0]), "=r"(r[1]), "=r"(r[2]), "=r"(r[3]) : "r"(addr));
}
__device__ __forceinline__ void mma_bf16(float* c, const uint32_t* a, uint32_t b0, uint32_t b1) {
    asm volatile("mma.sync.aligned.m16n8k16.row.col.f32.bf16.bf16.f32 "
        "{%0,%1,%2,%3}, {%4,%5,%6,%7}, {%8,%9}, {%0,%1,%2,%3};"
        : "+f"(c[0]), "+f"(c[1]), "+f"(c[2]), "+f"(c[3])
        : "r"(a[0]), "r"(a[1]), "r"(a[2]), "r"(a[3]), "r"(b0), "r"(b1));
}
#define CP_ASYNC(dst, src) asm volatile("cp.async.cg.shared.global [%0], [%1], 16;" :: "r"(dst), "l"(src))
#define CP_COMMIT()        asm volatile("cp.async.commit_group;" ::: "memory")
#define CP_WAIT(n)         asm volatile("cp.async.wait_group %0;" :: "n"(n) : "memory")

// ---------------- scratch ----------------
__device__ float g_bufB[(size_t)BATCH * NMAX * CDIM];
__device__ float g_sizeB[BATCH * NMAX];
__device__ __nv_bfloat16 g_msplit[(size_t)BATCH * P0 * 192];   // [h1|h2|h3] per token
__device__ float g_nodemax[BATCH * NMAX];
__device__ int   g_nodeidx[BATCH * NMAX];
__device__ float g_hsum[(size_t)BATCH * NMAX * 64];
__device__ float g_possum[P0 * 64];
__device__ int   g_edge[BATCH * 72];
__device__ __nv_bfloat16 g_A1[(size_t)1024 * 2048];    // GEMM1 A' [hi|lo]
__device__ __nv_bfloat16 g_A2[(size_t)1024 * 8192];    // GEMM2 A' [hi|lo]
__device__ __nv_bfloat16 g_W1b[(size_t)4096 * 2048];   // W1' [N,2K] [hi|lo]
__device__ __nv_bfloat16 g_W2b[(size_t)4096 * 8192];   // W2' [N,2K] [hi|lo]

__device__ __forceinline__ void bsplit(float x, unsigned short& h, unsigned short& l) {
    __nv_bfloat16 hb = __float2bfloat16(x);
    float r = x - __bfloat162float(hb);
    __nv_bfloat16 lb = __float2bfloat16(r);
    h = __bfloat16_as_ushort(hb);
    l = __bfloat16_as_ushort(lb);
}

__device__ __forceinline__ void msplit_write(__nv_bfloat16* o, int d, float v) {
    __nv_bfloat16 h1 = __float2bfloat16(v);
    float r1v = v - __bfloat162float(h1);
    __nv_bfloat16 h2 = __float2bfloat16(r1v);
    float r2v = r1v - __bfloat162float(h2);
    __nv_bfloat16 h3 = __float2bfloat16(r2v);
    o[d] = h1; o[64 + d] = h2; o[128 + d] = h3;
}

// ---------------- pos head-sum precompute ----------------
__global__ __launch_bounds__(256) void k_possum(const float* __restrict__ pos,
        float* __restrict__ possum)
{
    int idx = blockIdx.x * 256 + threadIdx.x;
    int t = idx >> 6, d = idx & 63;
    const float* pb = pos + (size_t)t * CDIM;
    float s = 0.f;
    #pragma unroll
    for (int h = 0; h < HEADS; ++h) s += pb[h * DDIM + d];
    possum[idx] = s;
}

// ---------------- metric round 1 ----------------
__global__ __launch_bounds__(256) void k_metric(const float* __restrict__ ws,
        const float* __restrict__ possum, __nv_bfloat16* __restrict__ msplit, int p)
{
    int tid = threadIdx.x;
    int sub = tid >> 6;
    int d   = tid & 63;
    int t   = blockIdx.x * 4 + sub;
    int tok = t % p;
    const float* base = ws + (size_t)t * CDIM;
    float s = 0.f;
    #pragma unroll
    for (int h = 0; h < HEADS; ++h) s += base[h * DDIM + d];
    s += possum[tok * 64 + d];
    float m = s * (1.f / 16.f);
    __shared__ float red[256];
    red[tid] = m * m;
    __syncthreads();
    for (int off = 32; off > 0; off >>= 1) {
        if (d < off) red[tid] += red[tid + off];
        __syncthreads();
    }
    float nrm = sqrtf(red[sub * 64]);
    msplit_write(msplit + (size_t)t * 192, d, m / nrm);
}

// ---------------- metric rounds 2-6: strided hsum rows ----------------
__global__ __launch_bounds__(256) void k_metric_h(const float* __restrict__ hsum,
        __nv_bfloat16* __restrict__ msplit, int p, int off0, int S)
{
    int tid = threadIdx.x;
    int sub = tid >> 6;
    int d   = tid & 63;
    int tc  = blockIdx.x * 4 + sub;       // compact index 0..B*p-1
    int b   = tc / p, t = tc - b * p;
    float m = hsum[((size_t)b * NMAX + off0 + t * S) * 64 + d] * (1.f / 16.f);
    __shared__ float red[256];
    red[tid] = m * m;
    __syncthreads();
    for (int off = 32; off > 0; off >>= 1) {
        if (d < off) red[tid] += red[tid + off];
        __syncthreads();
    }
    float nrm = sqrtf(red[sub * 64]);
    msplit_write(msplit + (size_t)tc * 192, d, m / nrm);
}

// ---------------- tensor-core scores + row argmax, bf16x6, cp.async triple-buffered B ----------------
#define AMSPAD 200
#define ABUF (128 * AMSPAD * 2)

__global__ __launch_bounds__(256) void k_argmax(const __nv_bfloat16* __restrict__ msplit,
        float* __restrict__ nodemax, int* __restrict__ nodeidx, int n, int p)
{
    extern __shared__ __align__(16) char dyn[];
    __nv_bfloat16* sA = (__nv_bfloat16*)dyn;
    uint32_t saA  = smem_u32(sA);
    uint32_t saB  = saA + 64 * AMSPAD * 2;      // 3 x [128][AMSPAD]
    float* sv = (float*)(dyn + 64 * AMSPAD * 2 + 3 * ABUF);
    int*   sj = (int*)  (dyn + 64 * AMSPAD * 2 + 3 * ABUF + 4 * 64 * 4);

    int b = blockIdx.y;
    int ibase = blockIdx.x * 64;
    const __nv_bfloat16* M = msplit + (size_t)b * p * 192;
    int tid = threadIdx.x;
    int wid = tid >> 5, lane = tid & 31;
    int wm = wid >> 2, wn = wid & 3;
    int g = lane >> 2, tg = lane & 3;

    int ntiles = (n + 127) >> 7;

    for (int o = tid; o < 64 * 24; o += 256) {
        int r = o / 24, s = o % 24;
        CP_ASYNC(saA + (uint32_t)(r * AMSPAD + s * 8) * 2,
                 M + (size_t)(2 * (ibase + r)) * 192 + s * 8);
    }
    for (int o = tid; o < 128 * 24; o += 256) {
        int r = o / 24, s = o % 24;
        CP_ASYNC(saB + (uint32_t)(r * AMSPAD + s * 8) * 2,
                 M + (size_t)(2 * r + 1) * 192 + s * 8);
    }
    CP_COMMIT();
    if (ntiles > 1) {
        for (int o = tid; o < 128 * 24; o += 256) {
            int r = o / 24, s = o % 24;
            CP_ASYNC(saB + ABUF + (uint32_t)(r * AMSPAD + s * 8) * 2,
                     M + (size_t)(2 * (128 + r) + 1) * 192 + s * 8);
        }
        CP_COMMIT();
    }

    float runv[4]; int runj[4];
    #pragma unroll
    for (int q = 0; q < 4; q++) { runv[q] = -1e30f; runj[q] = 0x7FFFFFFF; }

    const int amap[6] = {0, 0, 1, 1, 0, 2};
    const int bmap[6] = {0, 1, 0, 1, 2, 0};

    for (int jt = 0; jt < ntiles; jt++) {
        int jbase = jt << 7;
        uint32_t cb = saB + (uint32_t)(jt % 3) * ABUF;
        if (jt + 2 < ntiles) {
            uint32_t nb = saB + (uint32_t)((jt + 2) % 3) * ABUF;
            int jb2 = (jt + 2) << 7;
            for (int o = tid; o < 128 * 24; o += 256) {
                int r = o / 24, s = o % 24;
                CP_ASYNC(nb + (uint32_t)(r * AMSPAD + s * 8) * 2,
                         M + (size_t)(2 * (jb2 + r) + 1) * 192 + s * 8);
            }
            CP_COMMIT();
            CP_WAIT(2);
        } else if (jt + 1 < ntiles) {
            CP_WAIT(1);
        } else {
            CP_WAIT(0);
        }
        __syncthreads();

        float acc[2][4][4];
        #pragma unroll
        for (int mt = 0; mt < 2; mt++)
            #pragma unroll
            for (int nt = 0; nt < 4; nt++)
                #pragma unroll
                for (int q = 0; q < 4; q++) acc[mt][nt][q] = 0.f;

        #pragma unroll
        for (int blk = 0; blk < 6; blk++) {
            #pragma unroll
            for (int qk = 0; qk < 4; qk++) {
                int ca = amap[blk] * 64 + qk * 16 + (lane >> 4) * 8;
                int cbo = bmap[blk] * 64 + qk * 16 + (lane >> 4) * 8;
                uint32_t a[2][4], bb[2][4];
                #pragma unroll
                for (int mt = 0; mt < 2; mt++)
                    ldsm4(a[mt], saA + (uint32_t)((wm * 32 + mt * 16 + (lane & 15)) * AMSPAD + ca) * 2);
                #pragma unroll
                for (int nt2 = 0; nt2 < 2; nt2++)
                    ldsm4(bb[nt2], cb + (uint32_t)((wn * 32 + nt2 * 16 + (lane & 15)) * AMSPAD + cbo) * 2);
                #pragma unroll
                for (int mt = 0; mt < 2; mt++)
                    #pragma unroll
                    for (int nt = 0; nt < 4; nt++)
                        mma_bf16(acc[mt][nt], a[mt], bb[nt >> 1][nt & 1], bb[nt >> 1][(nt & 1) + 2]);
            }
        }

        #pragma unroll
        for (int mt = 0; mt < 2; mt++) {
            #pragma unroll
            for (int h = 0; h < 2; h++) {
                float bv = -1e30f; int bj = 0x7FFFFFFF;
                #pragma unroll
                for (int nt = 0; nt < 4; nt++) {
                    #pragma unroll
                    for (int q = 0; q < 2; q++) {
                        int jg = jbase + wn * 32 + nt * 8 + tg * 2 + q;
                        float v = acc[mt][nt][h * 2 + q];
                        if (jg < n && v > bv) { bv = v; bj = jg; }
                    }
                }
                int slot = mt * 2 + h;
                if (bv > runv[slot] || (bv == runv[slot] && bj < runj[slot])) {
                    runv[slot] = bv; runj[slot] = bj;
                }
            }
        }
        __syncthreads();
    }

    #pragma unroll
    for (int slot = 0; slot < 4; slot++) {
        float bv = runv[slot]; int bj = runj[slot];
        #pragma unroll
        for (int off = 1; off <= 2; off <<= 1) {
            float ov = __shfl_xor_sync(0xffffffffu, bv, off);
            int   oj = __shfl_xor_sync(0xffffffffu, bj, off);
            if (ov > bv || (ov == bv && oj < bj)) { bv = ov; bj = oj; }
        }
        runv[slot] = bv; runj[slot] = bj;
    }
    if (tg == 0) {
        #pragma unroll
        for (int slot = 0; slot < 4; slot++) {
            int mt = slot >> 1, h = slot & 1;
            int row = wm * 32 + mt * 16 + h * 8 + g;
            sv[wn * 64 + row] = runv[slot];
            sj[wn * 64 + row] = runj[slot];
        }
    }
    __syncthreads();
    if (tid < 64) {
        float bv = sv[tid]; int bj = sj[tid];
        #pragma unroll
        for (int w = 1; w < 4; w++) {
            float ov = sv[w * 64 + tid]; int oj = sj[w * 64 + tid];
            if (ov > bv || (ov == bv && oj < bj)) { bv = ov; bj = oj; }
        }
        int ig = ibase + tid;
        if (ig < n) {
            nodemax[b * NMAX + ig] = bv;
            nodeidx[b * NMAX + ig] = bj;
        }
    }
}
#define ARGMAX_SMEM (64 * AMSPAD * 2 + 3 * ABUF + 4 * 64 * 4 * 2)

// ---------------- round 1 merge (compact into bufB, with head-sum emission) ----------------
__global__ void k_dst_init(const float* __restrict__ ws, const float* __restrict__ pos,
        float* __restrict__ wsout, float* __restrict__ szout, float* __restrict__ hsum)
{
    const int n = 2304, p = 4608;
    __shared__ float sred[1024];
    int blk = blockIdx.x;
    int b = blk / n, j = blk % n;
    const float4* src = (const float4*)(ws + ((size_t)b * p + 2 * j + 1) * CDIM);
    float4* dst = (float4*)(wsout + ((size_t)b * NMAX + j) * CDIM);
    int c = threadIdx.x;
    float4 v = src[c];
    const float4* pb = (const float4*)(pos + (size_t)(2 * j + 1) * CDIM);
    float4 pv = pb[c];
    v.x += pv.x; v.y += pv.y; v.z += pv.z; v.w += pv.w;
    dst[c] = v;
    int c0 = c * 4;
    sred[c0] = v.x; sred[c0 + 1] = v.y; sred[c0 + 2] = v.z; sred[c0 + 3] = v.w;
    if (threadIdx.x == 0) szout[b * NMAX + j] = 1.f;
    __syncthreads();
    if (threadIdx.x < 64) {
        float s = 0.f;
        #pragma unroll
        for (int k = 0; k < 16; k++) s += sred[threadIdx.x + 64 * k];
        hsum[((size_t)b * NMAX + j) * 64 + threadIdx.x] = s;
    }
}

__global__ void k_scatter(const float* __restrict__ ws, const float* __restrict__ pos,
        const int* __restrict__ nodeidx, float* __restrict__ wsout, float* __restrict__ szout,
        float* __restrict__ hsum)
{
    const int n = 2304, p = 4608;
    __shared__ float sred[1024];
    int blk = blockIdx.x;
    int b = blk / n, i = blk % n;
    int j = nodeidx[b * NMAX + i];
    const float* src = ws + ((size_t)b * p + 2 * i) * CDIM;
    float* dst = wsout + ((size_t)b * NMAX + j) * CDIM;
    const float* pb = pos + (size_t)(2 * i) * CDIM;
    for (int c = threadIdx.x; c < CDIM; c += 256) {
        float val = src[c] + pb[c];
        atomicAdd(dst + c, val);
        sred[c] = val;
    }
    if (threadIdx.x == 0) atomicAdd(szout + b * NMAX + j, 1.f);
    __syncthreads();
    if (threadIdx.x < 64) {
        float s = 0.f;
        #pragma unroll
        for (int k = 0; k < 16; k++) s += sred[threadIdx.x + 64 * k];
        atomicAdd(&hsum[((size_t)b * NMAX + j) * 64 + threadIdx.x], s);
    }
}

// ---------------- rounds 2-5: in-place strided scatter merge ----------------
__global__ void k_scatter_ip(float* __restrict__ ws, float* __restrict__ sz,
        float* __restrict__ hsum, const int* __restrict__ nodeidx, int n, int off0, int S)
{
    int blk = blockIdx.x;
    int b = blk / n, i = blk % n;
    int j = nodeidx[b * NMAX + i];
    int srcpos = off0 + 2 * i * S;
    int dstpos = off0 + (2 * j + 1) * S;
    const float* src = ws + ((size_t)b * NMAX + srcpos) * CDIM;
    float* dst = ws + ((size_t)b * NMAX + dstpos) * CDIM;
    for (int c = threadIdx.x; c < CDIM; c += 256)
        atomicAdd(dst + c, src[c]);
    if (threadIdx.x == 0)
        atomicAdd(&sz[b * NMAX + dstpos], sz[b * NMAX + srcpos]);
    if (threadIdx.x >= 64 && threadIdx.x < 128) {
        int d = threadIdx.x - 64;
        atomicAdd(&hsum[((size_t)b * NMAX + dstpos) * 64 + d],
                  hsum[((size_t)b * NMAX + srcpos) * 64 + d]);
    }
}

// ---------------- round 6 ----------------
__global__ void k_sort6(const float* __restrict__ nodemax, int* __restrict__ edge)
{
    __shared__ float v[72];
    int b = blockIdx.x, t = threadIdx.x;
    if (t < 72) v[t] = nodemax[b * NMAX + t];
    __syncthreads();
    if (t < 72) {
        float mv = v[t];
        int rank = 0;
        for (int j2 = 0; j2 < 72; j2++) {
            float o = v[j2];
            if (o > mv || (o == mv && j2 < t)) rank++;
        }
        edge[b * 72 + rank] = t;
    }
}

// round 6 merge (input at positions 15+16t in bufB), fused /size + bf16 split -> A1
__global__ void k_round6(const float* __restrict__ ws, const float* __restrict__ sz,
        const int* __restrict__ nodeidx, const int* __restrict__ edge,
        __nv_bfloat16* __restrict__ A1)
{
    const int r = 16, u = 56;
    int b = blockIdx.y, t = blockIdx.x;
    int tid = threadIdx.x;
    const float* wsb = ws + (size_t)b * NMAX * CDIM;
    int m = b * 128 + t;
    __nv_bfloat16* rowp = A1 + (size_t)m * 2048;
    int c0 = tid * 4;

    float v[4];
    float s;
    if (t < u) {
        int e = edge[b * 72 + r + t];
        int pos = 15 + 32 * e;                 // even token 2e
        const float4 vv = ((const float4*)(wsb + (size_t)pos * CDIM))[tid];
        v[0] = vv.x; v[1] = vv.y; v[2] = vv.z; v[3] = vv.w;
        s = sz[b * NMAX + pos];
    } else {
        int j = t - u;
        int basepos = 31 + 32 * j;             // odd token 2j+1
        __shared__ int msrc[16];
        __shared__ int mcount;
        __shared__ float ssum_sh;
        if (tid == 0) {
            int cnt = 0;
            float ssum = sz[b * NMAX + basepos];
            for (int q = 0; q < r; q++) {
                int e = edge[b * 72 + q];
                if (nodeidx[b * NMAX + e] == j) {
                    msrc[cnt++] = 15 + 32 * e;
                    ssum += sz[b * NMAX + 15 + 32 * e];
                }
            }
            mcount = cnt;
            ssum_sh = ssum;
        }
        __syncthreads();
        int cnt = mcount;
        s = ssum_sh;
        const float4 base4 = ((const float4*)(wsb + (size_t)basepos * CDIM))[tid];
        v[0] = base4.x; v[1] = base4.y; v[2] = base4.z; v[3] = base4.w;
        for (int q = 0; q < cnt; q++) {
            const float4 a4 = ((const float4*)(wsb + (size_t)msrc[q] * CDIM))[tid];
            v[0] += a4.x; v[1] += a4.y; v[2] += a4.z; v[3] += a4.w;
        }
    }
    float inv = 1.f / s;
    unsigned short hh[4], ll[4];
    #pragma unroll
    for (int q = 0; q < 4; q++) bsplit(v[q] * inv, hh[q], ll[q]);
    uint2 hp, lp;
    hp.x = (uint32_t)hh[0] | ((uint32_t)hh[1] << 16);
    hp.y = (uint32_t)hh[2] | ((uint32_t)hh[3] << 16);
    lp.x = (uint32_t)ll[0] | ((uint32_t)ll[1] << 16);
    lp.y = (uint32_t)ll[2] | ((uint32_t)ll[3] << 16);
    *(uint2*)(rowp + c0)        = hp;
    *(uint2*)(rowp + 1024 + c0) = lp;
}

// ---------------- conversions ----------------
__global__ void k_convW(const float* __restrict__ W, __nv_bfloat16* __restrict__ Bp,
                        int K, int N)
{
    __shared__ float tile[32][33];
    int n0 = blockIdx.x * 32, k0 = blockIdx.y * 32;
    int tx = threadIdx.x & 31, ty = threadIdx.x >> 5;
    #pragma unroll
    for (int i = 0; i < 4; i++)
        tile[ty + 8 * i][tx] = W[(size_t)(k0 + ty + 8 * i) * N + n0 + tx];
    __syncthreads();
    size_t s2K = (size_t)2 * K;
    #pragma unroll
    for (int i = 0; i < 4; i++) {
        float v = tile[tx][ty + 8 * i];
        unsigned short h, l;
        bsplit(v, h, l);
        __nv_bfloat16* row = Bp + (size_t)(n0 + ty + 8 * i) * s2K + k0 + tx;
        row[0] = __ushort_as_bfloat16(h);
        row[K] = __ushort_as_bfloat16(l);
    }
}

// ---------------- warp-MMA bf16 GEMM (MLP), BK=32, 3-stage, deduped [hi|lo] storage ----------------
#define SMPAD 40
#define MMBUF (128 * SMPAD * 2)
#define MM_SMEM (6 * MMBUF)

template<int EPI>
__global__ __launch_bounds__(256) void k_mma(
    const __nv_bfloat16* __restrict__ A, int lda,
    const __nv_bfloat16* __restrict__ B, int ldb,
    const float* __restrict__ bias,
    float* __restrict__ outF, __nv_bfloat16* __restrict__ outS, int K, int nchunk3)
{
    extern __shared__ __align__(16) char dynm[];
    uint32_t saA = smem_u32(dynm);
    uint32_t saB = saA + 3 * MMBUF;

    int tid = threadIdx.x;
    int wid = tid >> 5, lane = tid & 31;
    int wm = wid >> 2, wn = wid & 3;
    int m0 = blockIdx.y * 128, n0 = blockIdx.x * 128;

    float acc[4][4][4];
    #pragma unroll
    for (int i = 0; i < 4; i++)
        #pragma unroll
        for (int j = 0; j < 4; j++)
            #pragma unroll
            for (int q = 0; q < 4; q++) acc[i][j][q] = 0.f;

    int lrow = tid >> 2;
    int lseg = tid & 3;
    uint32_t soff0 = (uint32_t)(lrow * SMPAD + lseg * 8) * 2;
    uint32_t soff1 = (uint32_t)((lrow + 64) * SMPAD + lseg * 8) * 2;

    const __nv_bfloat16* Abase = A + (size_t)(m0 + lrow) * lda + lseg * 8;
    const __nv_bfloat16* Bbase = B + (size_t)(n0 + lrow) * ldb + lseg * 8;
    size_t astep64 = (size_t)64 * lda;
    size_t bstep64 = (size_t)64 * ldb;

    int ntile = K >> 5;

    auto issue = [&](int ic, int stage) {
        int blk = ic / nchunk3;
        int rem = ic - blk * nchunk3;
        int achunk = ((blk == 1) ? nchunk3 : 0) + rem;
        int bchunk = ((blk == 2) ? nchunk3 : 0) + rem;
        const __nv_bfloat16* Ap = Abase + (size_t)achunk * 32;
        const __nv_bfloat16* Bp = Bbase + (size_t)bchunk * 32;
        uint32_t da = saA + stage * MMBUF;
        uint32_t db = saB + stage * MMBUF;
        CP_ASYNC(da + soff0, Ap);
        CP_ASYNC(da + soff1, Ap + astep64);
        CP_ASYNC(db + soff0, Bp);
        CP_ASYNC(db + soff1, Bp + bstep64);
        CP_COMMIT();
    };

    issue(0, 0);
    if (ntile > 1) issue(1, 1);

    for (int it = 0; it < ntile; it++) {
        int stage = it % 3;
        if (it + 2 < ntile) {
            issue(it + 2, (it + 2) % 3);
            CP_WAIT(2);
        } else if (it + 1 < ntile) {
            CP_WAIT(1);
        } else {
            CP_WAIT(0);
        }
        __syncthreads();

        uint32_t bufA = saA + stage * MMBUF;
        uint32_t bufB2 = saB + stage * MMBUF;
        #pragma unroll
        for (int ks = 0; ks < 2; ks++) {
            uint32_t a[4][4], b[2][4];
            int c = ks * 16 + (lane >> 4) * 8;
            #pragma unroll
            for (int mt = 0; mt < 4; mt++) {
                int r = wm * 64 + mt * 16 + (lane & 15);
                ldsm4(a[mt], bufA + (uint32_t)(r * SMPAD + c) * 2);
            }
            #pragma unroll
            for (int nt2 = 0; nt2 < 2; nt2++) {
                int r = wn * 32 + nt2 * 16 + (lane & 15);
                ldsm4(b[nt2], bufB2 + (uint32_t)(r * SMPAD + c) * 2);
            }
            #pragma unroll
            for (int mt = 0; mt < 4; mt++)
                #pragma unroll
                for (int nt = 0; nt < 4; nt++)
                    mma_bf16(acc[mt][nt], a[mt], b[nt >> 1][nt & 1], b[nt >> 1][(nt & 1) + 2]);
        }
        __syncthreads();
    }

    int g = lane >> 2, tg = lane & 3;
    #pragma unroll
    for (int mt = 0; mt < 4; mt++) {
        #pragma unroll
        for (int half = 0; half < 2; half++) {
            int m = m0 + wm * 64 + mt * 16 + g + half * 8;
            #pragma unroll
            for (int nt = 0; nt < 4; nt++) {
                int col = n0 + wn * 32 + nt * 8 + tg * 2;
                float2 bb = *(const float2*)(bias + col);
                float v0 = acc[mt][nt][half * 2 + 0] + bb.x;
                float v1 = acc[mt][nt][half * 2 + 1] + bb.y;
                if (EPI == 1) {
                    v0 = 0.5f * v0 * (1.f + erff(v0 * 0.70710678118654752f));
                    v1 = 0.5f * v1 * (1.f + erff(v1 * 0.70710678118654752f));
                    unsigned short h0, l0, h1, l1;
                    bsplit(v0, h0, l0);
                    bsplit(v1, h1, l1);
                    uint32_t hp = (uint32_t)h0 | ((uint32_t)h1 << 16);
                    uint32_t lp = (uint32_t)l0 | ((uint32_t)l1 << 16);
                    __nv_bfloat16* rowp = outS + (size_t)m * 8192;
                    *(uint32_t*)(rowp + col)        = hp;
                    *(uint32_t*)(rowp + col + 4096) = lp;
                } else {
                    float2 o; o.x = v0; o.y = v1;
                    *(float2*)(outF + (size_t)m * 4096 + col) = o;
                }
            }
        }
    }
}

// ---------------- launcher ----------------
extern "C" void kernel_launch(void* const* d_in, const int* in_sizes, int n_in,
                              void* d_out, int out_size)
{
    const float* x   = (const float*)d_in[0];
    const float* pos = (const float*)d_in[1];
    const float* W1  = (const float*)d_in[2];
    const float* b1  = (const float*)d_in[3];
    const float* W2  = (const float*)d_in[4];
    const float* b2  = (const float*)d_in[5];
    float* out = (float*)d_out;

    float *bufB, *szB, *nmax, *hsum, *possum;
    int *nidx, *edge;
    __nv_bfloat16 *msplit, *A1, *A2, *W1b, *W2b;
    cudaGetSymbolAddress((void**)&bufB,   g_bufB);
    cudaGetSymbolAddress((void**)&szB,    g_sizeB);
    cudaGetSymbolAddress((void**)&msplit, g_msplit);
    cudaGetSymbolAddress((void**)&nmax,   g_nodemax);
    cudaGetSymbolAddress((void**)&nidx,   g_nodeidx);
    cudaGetSymbolAddress((void**)&hsum,   g_hsum);
    cudaGetSymbolAddress((void**)&possum, g_possum);
    cudaGetSymbolAddress((void**)&edge,   g_edge);
    cudaGetSymbolAddress((void**)&A1,     g_A1);
    cudaGetSymbolAddress((void**)&A2,     g_A2);
    cudaGetSymbolAddress((void**)&W1b,    g_W1b);
    cudaGetSymbolAddress((void**)&W2b,    g_W2b);

    cudaFuncSetAttribute(k_argmax, cudaFuncAttributeMaxDynamicSharedMemorySize, ARGMAX_SMEM);
    cudaFuncSetAttribute(k_mma<1>, cudaFuncAttributeMaxDynamicSharedMemorySize, MM_SMEM);
    cudaFuncSetAttribute(k_mma<0>, cudaFuncAttributeMaxDynamicSharedMemorySize, MM_SMEM);

    // weight conversions + pos head-sum (independent of merge results)
    k_possum<<<P0 * 64 / 256, 256>>>(pos, possum);
    k_convW<<<dim3(4096 / 32, 1024 / 32), 256>>>(W1, W1b, 1024, 4096);
    k_convW<<<dim3(4096 / 32, 4096 / 32), 256>>>(W2, W2b, 4096, 4096);

    // Round 1: p=4608 -> 2304 tokens compact in bufB (off=0, S=1)
    k_metric<<<BATCH * 4608 / 4, 256>>>(x, possum, msplit, 4608);
    k_argmax<<<dim3(36, BATCH), 256, ARGMAX_SMEM>>>(msplit, nmax, nidx, 2304, 4608);
    k_dst_init<<<BATCH * 2304, 256>>>(x, pos, bufB, szB, hsum);
    k_scatter<<<BATCH * 2304, 256>>>(x, pos, nidx, bufB, szB, hsum);

    // Round 2: 2304 (off=0,S=1) -> survivors (off=1,S=2)
    k_metric_h<<<BATCH * 2304 / 4, 256>>>(hsum, msplit, 2304, 0, 1);
    k_argmax<<<dim3(18, BATCH), 256, ARGMAX_SMEM>>>(msplit, nmax, nidx, 1152, 2304);
    k_scatter_ip<<<BATCH * 1152, 256>>>(bufB, szB, hsum, nidx, 1152, 0, 1);

    // Round 3: 1152 (off=1,S=2) -> (off=3,S=4)
    k_metric_h<<<BATCH * 1152 / 4, 256>>>(hsum, msplit, 1152, 1, 2);
    k_argmax<<<dim3(9, BATCH), 256, ARGMAX_SMEM>>>(msplit, nmax, nidx, 576, 1152);
    k_scatter_ip<<<BATCH * 576, 256>>>(bufB, szB, hsum, nidx, 576, 1, 2);

    // Round 4: 576 (off=3,S=4) -> (off=7,S=8)
    k_metric_h<<<BATCH * 576 / 4, 256>>>(hsum, msplit, 576, 3, 4);
    k_argmax<<<dim3(5, BATCH), 256, ARGMAX_SMEM>>>(msplit, nmax, nidx, 288, 576);
    k_scatter_ip<<<BATCH * 288, 256>>>(bufB, szB, hsum, nidx, 288, 3, 4);

    // Round 5: 288 (off=7,S=8) -> (off=15,S=16)
    k_metric_h<<<BATCH * 288 / 4, 256>>>(hsum, msplit, 288, 7, 8);
    k_argmax<<<dim3(3, BATCH), 256, ARGMAX_SMEM>>>(msplit, nmax, nidx, 144, 288);
    k_scatter_ip<<<BATCH * 144, 256>>>(bufB, szB, hsum, nidx, 144, 7, 8);

    // Round 6: 144 tokens at (off=15,S=16); n=72, r=16; fused output -> A1 [hi|lo]
    k_metric_h<<<BATCH * 144 / 4, 256>>>(hsum, msplit, 144, 15, 16);
    k_argmax<<<dim3(2, BATCH), 256, ARGMAX_SMEM>>>(msplit, nmax, nidx, 72, 144);
    k_sort6<<<BATCH, 128>>>(nmax, edge);
    k_round6<<<dim3(128, BATCH), 256>>>(bufB, szB, nidx, edge, A1);

    // GEMM1: gelu((A/sz)@W1+b1) -> [hi|lo] into A2. logical K=3072, nchunk3=32
    k_mma<1><<<dim3(32, 8), 256, MM_SMEM>>>(A1, 2048, W1b, 2048, b1, nullptr, A2, 3072, 32);
    // GEMM2: A2@W2+b2 -> out fp32. logical K=12288, nchunk3=128
    k_mma<0><<<dim3(32, 8), 256, MM_SMEM>>>(A2, 8192, W2b, 8192, b2, out, nullptr, 12288, 128);
}